// round 12
// baseline (speedup 1.0000x reference)
#include <cuda_runtime.h>
#include <cuda_fp16.h>
#include <math.h>

#define D 128
#define MAX_NODES 131072        // >= 100000 actual
#define SMEM_CAP_NODES 102400   // 200 KB of fp16 — max table we place in smem

// Per-node projections in fp16 (precision validated R10: rel_err 8e-5).
__device__ __half g_pu[MAX_NODES];
__device__ __half g_pv[MAX_NODES];

// ---------------------------------------------------------------------------
// Kernel 1: projections. 8 lanes per node, 4 nodes per warp.
// At the HBM stream roofline (~6.5 TB/s). Unchanged.
// ---------------------------------------------------------------------------
__global__ __launch_bounds__(256) void proj_kernel(
    const float* __restrict__ h,
    const float* __restrict__ W,   // [256]: Wu=W[0:128], Wv=W[128:256]
    int n_nodes)
{
    int lane = threadIdx.x & 31;
    int sub  = lane >> 3;
    int c    = lane & 7;

    const float4* Wu4 = reinterpret_cast<const float4*>(W);
    const float4* Wv4 = reinterpret_cast<const float4*>(W + D);
    float4 wu[4], wv[4];
    #pragma unroll
    for (int it = 0; it < 4; it++) {
        wu[it] = Wu4[it * 8 + c];
        wv[it] = Wv4[it * 8 + c];
    }

    int gwarp = (blockIdx.x * blockDim.x + threadIdx.x) >> 5;
    int node  = gwarp * 4 + sub;

    float su = 0.0f, sv = 0.0f;
    if (node < n_nodes) {
        const float4* hp = reinterpret_cast<const float4*>(h + (size_t)node * D);
        float4 hv[4];
        #pragma unroll
        for (int it = 0; it < 4; it++)
            hv[it] = __ldcs(&hp[it * 8 + c]);
        #pragma unroll
        for (int it = 0; it < 4; it++) {
            su += hv[it].x * wu[it].x + hv[it].y * wu[it].y
                + hv[it].z * wu[it].z + hv[it].w * wu[it].w;
            sv += hv[it].x * wv[it].x + hv[it].y * wv[it].y
                + hv[it].z * wv[it].z + hv[it].w * wv[it].w;
        }
    }

    #pragma unroll
    for (int o = 4; o >= 1; o >>= 1) {
        su += __shfl_xor_sync(0xFFFFFFFFu, su, o);
        sv += __shfl_xor_sync(0xFFFFFFFFu, sv, o);
    }
    if (c == 0 && node < n_nodes) {
        g_pu[node] = __float2half(su);
        g_pv[node] = __float2half(sv);
    }
}

// ---------------------------------------------------------------------------
// Kernel 2 (new mechanism): pu table in SHARED MEMORY.
// 148 blocks x 1024 threads, 200KB dynamic smem -> 1 block/SM, single wave.
// Phase A: block copies the whole fp16 pu table into smem (coalesced float4
//          reads; table is L2-resident after the first block touches it).
// Phase B: grid-stride over edge quads:
//          pu[src] via LDS  (halves the l1tex LDG wavefront count),
//          pv[dst] via LDG  (L1 now holds mostly the 200KB pv table -> hits).
// ---------------------------------------------------------------------------
__global__ __launch_bounds__(1024, 1) void edge_kernel_smem(
    const int*  __restrict__ src,
    const int*  __restrict__ dst,
    const float* __restrict__ bias,
    float* __restrict__ out,
    int n_nodes,
    int n_quads)                   // total_edges / 4
{
    extern __shared__ __half s_pu[];

    // Phase A: cooperative table load, float4 = 8 halves per transaction
    {
        int n_vec = (n_nodes + 7) / 8;   // g_pu is padded (MAX_NODES) — safe
        const float4* srcv = reinterpret_cast<const float4*>(g_pu);
        float4* dstv = reinterpret_cast<float4*>(s_pu);
        for (int i = threadIdx.x; i < n_vec; i += blockDim.x)
            dstv[i] = srcv[i];
    }
    __syncthreads();

    // Phase B: edge loop
    float b = bias[0];
    int tid = blockIdx.x * blockDim.x + threadIdx.x;
    int nthreads = gridDim.x * blockDim.x;

    for (int i = tid; i < n_quads; i += nthreads) {
        int4 s = reinterpret_cast<const int4*>(src)[i];
        int4 d = reinterpret_cast<const int4*>(dst)[i];

        // pu from smem (LDS), pv from global (LDG) — all issued before math
        float u0 = __half2float(s_pu[s.x]);
        float u1 = __half2float(s_pu[s.y]);
        float u2 = __half2float(s_pu[s.z]);
        float u3 = __half2float(s_pu[s.w]);
        float v0 = __half2float(g_pv[d.x]);
        float v1 = __half2float(g_pv[d.y]);
        float v2 = __half2float(g_pv[d.z]);
        float v3 = __half2float(g_pv[d.w]);

        float4 o;
        o.x = 1.0f / (1.0f + expf(-(u0 + v0 + b)));
        o.y = 1.0f / (1.0f + expf(-(u1 + v1 + b)));
        o.z = 1.0f / (1.0f + expf(-(u2 + v2 + b)));
        o.w = 1.0f / (1.0f + expf(-(u3 + v3 + b)));

        reinterpret_cast<float4*>(out)[i] = o;
    }
}

// Fallback edge kernel (proven R2/R8 shape) — used only if the node table
// exceeds smem capacity.
__global__ __launch_bounds__(256) void edge_kernel_fallback(
    const int*  __restrict__ src,
    const int*  __restrict__ dst,
    const float* __restrict__ bias,
    float* __restrict__ out,
    int n_quads)
{
    int i = blockIdx.x * blockDim.x + threadIdx.x;
    if (i >= n_quads) return;

    float b = bias[0];
    int4 s = reinterpret_cast<const int4*>(src)[i];
    int4 d = reinterpret_cast<const int4*>(dst)[i];

    float u0 = __half2float(g_pu[s.x]), u1 = __half2float(g_pu[s.y]);
    float u2 = __half2float(g_pu[s.z]), u3 = __half2float(g_pu[s.w]);
    float v0 = __half2float(g_pv[d.x]), v1 = __half2float(g_pv[d.y]);
    float v2 = __half2float(g_pv[d.z]), v3 = __half2float(g_pv[d.w]);

    float4 o;
    o.x = 1.0f / (1.0f + expf(-(u0 + v0 + b)));
    o.y = 1.0f / (1.0f + expf(-(u1 + v1 + b)));
    o.z = 1.0f / (1.0f + expf(-(u2 + v2 + b)));
    o.w = 1.0f / (1.0f + expf(-(u3 + v3 + b)));

    reinterpret_cast<float4*>(out)[i] = o;
}

__global__ void edge_kernel_tail(
    const int*  __restrict__ src,
    const int*  __restrict__ dst,
    const float* __restrict__ bias,
    float* __restrict__ out,
    int start, int n_edges)
{
    int i = start + blockIdx.x * blockDim.x + threadIdx.x;
    if (i >= n_edges) return;
    float x = __half2float(g_pu[src[i]]) + __half2float(g_pv[dst[i]]) + bias[0];
    out[i] = 1.0f / (1.0f + expf(-x));
}

extern "C" void kernel_launch(void* const* d_in, const int* in_sizes, int n_in,
                              void* d_out, int out_size)
{
    const float* h      = (const float*)d_in[0];
    const int*   src    = (const int*)  d_in[1];
    const int*   dst    = (const int*)  d_in[2];
    const float* W      = (const float*)d_in[3];
    const float* W_bias = (const float*)d_in[4];
    float* out          = (float*)d_out;

    int n_nodes = in_sizes[0] / D;
    int n_edges = in_sizes[1];

    // Kernel 1: projections
    {
        int n_groups = (n_nodes + 3) / 4;
        int blocks = (n_groups * 32 + 255) / 256;
        proj_kernel<<<blocks, 256>>>(h, W, n_nodes);
    }

    // Kernel 2
    int n_quads = n_edges / 4;
    if (n_nodes <= SMEM_CAP_NODES) {
        // Round smem size up to float4 multiple to cover the vector copy
        int n_vec = (n_nodes + 7) / 8;
        size_t smem_bytes = (size_t)n_vec * 16;
        cudaFuncSetAttribute(edge_kernel_smem,
                             cudaFuncAttributeMaxDynamicSharedMemorySize,
                             (int)smem_bytes);
        if (n_quads > 0)
            edge_kernel_smem<<<148, 1024, smem_bytes>>>(
                src, dst, W_bias, out, n_nodes, n_quads);
    } else {
        if (n_quads > 0) {
            int blocks = (n_quads + 255) / 256;
            edge_kernel_fallback<<<blocks, 256>>>(src, dst, W_bias, out, n_quads);
        }
    }

    int tail_start = n_quads * 4;
    int tail = n_edges - tail_start;
    if (tail > 0)
        edge_kernel_tail<<<(tail + 255) / 256, 256>>>(src, dst, W_bias, out,
                                                      tail_start, n_edges);
}

// round 13
// speedup vs baseline: 1.1004x; 1.1004x over previous
#include <cuda_runtime.h>
#include <math.h>

#define D 128
#define MAX_NODES 131072   // >= 100000 actual

// Per-node projections h[n]·Wu, h[n]·Wv.
__device__ float g_pu[MAX_NODES];
__device__ float g_pv[MAX_NODES];

// ---------------------------------------------------------------------------
// Kernel 1: projections. 8 lanes per node, 4 nodes per warp.
// Measured at the HBM stream roofline (~6.5 TB/s, 81% of spec).
// ---------------------------------------------------------------------------
__global__ __launch_bounds__(256) void proj_kernel(
    const float* __restrict__ h,
    const float* __restrict__ W,   // [256]: Wu=W[0:128], Wv=W[128:256]
    int n_nodes)
{
    int lane = threadIdx.x & 31;
    int sub  = lane >> 3;
    int c    = lane & 7;

    const float4* Wu4 = reinterpret_cast<const float4*>(W);
    const float4* Wv4 = reinterpret_cast<const float4*>(W + D);
    float4 wu[4], wv[4];
    #pragma unroll
    for (int it = 0; it < 4; it++) {
        wu[it] = Wu4[it * 8 + c];
        wv[it] = Wv4[it * 8 + c];
    }

    int gwarp = (blockIdx.x * blockDim.x + threadIdx.x) >> 5;
    int node  = gwarp * 4 + sub;

    float su = 0.0f, sv = 0.0f;
    if (node < n_nodes) {
        const float4* hp = reinterpret_cast<const float4*>(h + (size_t)node * D);
        float4 hv[4];
        #pragma unroll
        for (int it = 0; it < 4; it++)
            hv[it] = __ldcs(&hp[it * 8 + c]);   // h streamed exactly once
        #pragma unroll
        for (int it = 0; it < 4; it++) {
            su += hv[it].x * wu[it].x + hv[it].y * wu[it].y
                + hv[it].z * wu[it].z + hv[it].w * wu[it].w;
            sv += hv[it].x * wv[it].x + hv[it].y * wv[it].y
                + hv[it].z * wv[it].z + hv[it].w * wv[it].w;
        }
    }

    #pragma unroll
    for (int o = 4; o >= 1; o >>= 1) {
        su += __shfl_xor_sync(0xFFFFFFFFu, su, o);
        sv += __shfl_xor_sync(0xFFFFFFFFu, sv, o);
    }
    if (c == 0 && node < n_nodes) {
        g_pu[node] = su;
        g_pv[node] = sv;
    }
}

// ---------------------------------------------------------------------------
// Kernel 2: per-edge score — the empirically optimal configuration, measured
// fastest across 7 tested mechanisms (16.29/16.45us): 4 edges/thread,
// 256-thread blocks, plain loads, all 8 gathers issued before dependent math.
// Tested and rejected: 8/thr (+2.5us), .cs/.cg hints (+0.6-1.4us),
// fp16 tables + grid-stride (+0.9us), smem pu table (+6.9us).
// ---------------------------------------------------------------------------
__global__ __launch_bounds__(256) void edge_kernel(
    const int*  __restrict__ src,
    const int*  __restrict__ dst,
    const float* __restrict__ bias,
    float* __restrict__ out,
    int n_quads)                   // total_edges / 4
{
    int i = blockIdx.x * blockDim.x + threadIdx.x;
    if (i >= n_quads) return;

    float b = bias[0];
    int4 s = reinterpret_cast<const int4*>(src)[i];
    int4 d = reinterpret_cast<const int4*>(dst)[i];

    // All 8 gathers issued before any dependent math
    float u0 = g_pu[s.x], u1 = g_pu[s.y], u2 = g_pu[s.z], u3 = g_pu[s.w];
    float v0 = g_pv[d.x], v1 = g_pv[d.y], v2 = g_pv[d.z], v3 = g_pv[d.w];

    float x0 = u0 + v0 + b;
    float x1 = u1 + v1 + b;
    float x2 = u2 + v2 + b;
    float x3 = u3 + v3 + b;

    float4 o;
    o.x = 1.0f / (1.0f + expf(-x0));
    o.y = 1.0f / (1.0f + expf(-x1));
    o.z = 1.0f / (1.0f + expf(-x2));
    o.w = 1.0f / (1.0f + expf(-x3));

    reinterpret_cast<float4*>(out)[i] = o;
}

// Scalar tail (unused when n_edges % 4 == 0; 1.6M % 4 == 0)
__global__ void edge_kernel_tail(
    const int*  __restrict__ src,
    const int*  __restrict__ dst,
    const float* __restrict__ bias,
    float* __restrict__ out,
    int start, int n_edges)
{
    int i = start + blockIdx.x * blockDim.x + threadIdx.x;
    if (i >= n_edges) return;
    float x = g_pu[src[i]] + g_pv[dst[i]] + bias[0];
    out[i] = 1.0f / (1.0f + expf(-x));
}

extern "C" void kernel_launch(void* const* d_in, const int* in_sizes, int n_in,
                              void* d_out, int out_size)
{
    const float* h      = (const float*)d_in[0];
    const int*   src    = (const int*)  d_in[1];
    const int*   dst    = (const int*)  d_in[2];
    const float* W      = (const float*)d_in[3];
    const float* W_bias = (const float*)d_in[4];
    float* out          = (float*)d_out;

    int n_nodes = in_sizes[0] / D;
    int n_edges = in_sizes[1];

    // Kernel 1: 4 nodes per warp
    {
        int n_groups = (n_nodes + 3) / 4;
        int blocks = (n_groups * 32 + 255) / 256;
        proj_kernel<<<blocks, 256>>>(h, W, n_nodes);
    }

    // Kernel 2: 4 edges per thread, 256-thread blocks
    {
        int n_quads = n_edges / 4;
        if (n_quads > 0) {
            int blocks = (n_quads + 255) / 256;
            edge_kernel<<<blocks, 256>>>(src, dst, W_bias, out, n_quads);
        }
        int tail_start = n_quads * 4;
        int tail = n_edges - tail_start;
        if (tail > 0)
            edge_kernel_tail<<<(tail + 255) / 256, 256>>>(src, dst, W_bias, out,
                                                          tail_start, n_edges);
    }
}

// round 14
// speedup vs baseline: 1.1827x; 1.0749x over previous
#include <cuda_runtime.h>
#include <math.h>

#define D 128
#define MAX_NODES 131072   // >= 100000 actual

// Per-node projections. g_pu has the bias folded in (saves a per-edge FADD
// and the bias load in the edge kernel).
__device__ float g_pu[MAX_NODES];
__device__ float g_pv[MAX_NODES];

// ---------------------------------------------------------------------------
// Kernel 1: projections. 8 lanes per node, 4 nodes per warp.
// Measured at the HBM stream roofline (~6.5 TB/s, 81% of spec). Implicit PDL
// trigger at kernel end -> all pu/pv writes visible to the dependent kernel.
// ---------------------------------------------------------------------------
__global__ __launch_bounds__(256) void proj_kernel(
    const float* __restrict__ h,
    const float* __restrict__ W,    // [256]: Wu=W[0:128], Wv=W[128:256]
    const float* __restrict__ bias,
    int n_nodes)
{
    int lane = threadIdx.x & 31;
    int sub  = lane >> 3;
    int c    = lane & 7;

    const float4* Wu4 = reinterpret_cast<const float4*>(W);
    const float4* Wv4 = reinterpret_cast<const float4*>(W + D);
    float4 wu[4], wv[4];
    #pragma unroll
    for (int it = 0; it < 4; it++) {
        wu[it] = Wu4[it * 8 + c];
        wv[it] = Wv4[it * 8 + c];
    }

    int gwarp = (blockIdx.x * blockDim.x + threadIdx.x) >> 5;
    int node  = gwarp * 4 + sub;

    float su = 0.0f, sv = 0.0f;
    if (node < n_nodes) {
        const float4* hp = reinterpret_cast<const float4*>(h + (size_t)node * D);
        float4 hv[4];
        #pragma unroll
        for (int it = 0; it < 4; it++)
            hv[it] = __ldcs(&hp[it * 8 + c]);   // h streamed exactly once
        #pragma unroll
        for (int it = 0; it < 4; it++) {
            su += hv[it].x * wu[it].x + hv[it].y * wu[it].y
                + hv[it].z * wu[it].z + hv[it].w * wu[it].w;
            sv += hv[it].x * wv[it].x + hv[it].y * wv[it].y
                + hv[it].z * wv[it].z + hv[it].w * wv[it].w;
        }
    }

    #pragma unroll
    for (int o = 4; o >= 1; o >>= 1) {
        su += __shfl_xor_sync(0xFFFFFFFFu, su, o);
        sv += __shfl_xor_sync(0xFFFFFFFFu, sv, o);
    }
    if (c == 0 && node < n_nodes) {
        g_pu[node] = su + bias[0];   // bias folded into pu
        g_pv[node] = sv;
    }
}

// ---------------------------------------------------------------------------
// Kernel 2: per-edge score — proven optimal shape (4 edges/thread, 256-thr
// blocks, plain loads; fastest of 7 tested mechanisms at 16.3-17.2us), now
// PDL-enabled: launches as proj drains, runs its proj-INDEPENDENT preamble
// (index loads) concurrently with proj's tail, then grid-dependency-syncs
// before the pu/pv gathers. Correct with or without PDL taking effect.
// ---------------------------------------------------------------------------
__global__ __launch_bounds__(256) void edge_kernel(
    const int*  __restrict__ src,
    const int*  __restrict__ dst,
    float* __restrict__ out,
    int n_quads)                   // total_edges / 4
{
    int i = blockIdx.x * blockDim.x + threadIdx.x;
    bool active = (i < n_quads);

    // Preamble: independent of proj output — overlaps proj's tail under PDL
    int4 s = make_int4(0, 0, 0, 0), d = make_int4(0, 0, 0, 0);
    if (active) {
        s = reinterpret_cast<const int4*>(src)[i];
        d = reinterpret_cast<const int4*>(dst)[i];
    }

    cudaGridDependencySynchronize();   // wait for proj's pu/pv writes

    if (!active) return;

    // All 8 gathers issued before any dependent math
    float u0 = g_pu[s.x], u1 = g_pu[s.y], u2 = g_pu[s.z], u3 = g_pu[s.w];
    float v0 = g_pv[d.x], v1 = g_pv[d.y], v2 = g_pv[d.z], v3 = g_pv[d.w];

    float4 o;
    o.x = 1.0f / (1.0f + expf(-(u0 + v0)));
    o.y = 1.0f / (1.0f + expf(-(u1 + v1)));
    o.z = 1.0f / (1.0f + expf(-(u2 + v2)));
    o.w = 1.0f / (1.0f + expf(-(u3 + v3)));

    reinterpret_cast<float4*>(out)[i] = o;
}

// Scalar tail (unused when n_edges % 4 == 0; 1.6M % 4 == 0)
__global__ void edge_kernel_tail(
    const int*  __restrict__ src,
    const int*  __restrict__ dst,
    float* __restrict__ out,
    int start, int n_edges)
{
    int i = start + blockIdx.x * blockDim.x + threadIdx.x;
    if (i >= n_edges) return;
    float x = g_pu[src[i]] + g_pv[dst[i]];   // bias already folded into pu
    out[i] = 1.0f / (1.0f + expf(-x));
}

extern "C" void kernel_launch(void* const* d_in, const int* in_sizes, int n_in,
                              void* d_out, int out_size)
{
    const float* h      = (const float*)d_in[0];
    const int*   src    = (const int*)  d_in[1];
    const int*   dst    = (const int*)  d_in[2];
    const float* W      = (const float*)d_in[3];
    const float* W_bias = (const float*)d_in[4];
    float* out          = (float*)d_out;

    int n_nodes = in_sizes[0] / D;
    int n_edges = in_sizes[1];

    // Kernel 1: projections (4 nodes per warp)
    {
        int n_groups = (n_nodes + 3) / 4;
        int blocks = (n_groups * 32 + 255) / 256;
        proj_kernel<<<blocks, 256>>>(h, W, W_bias, n_nodes);
    }

    // Kernel 2: PDL launch — overlaps its preamble with proj's tail
    {
        int n_quads = n_edges / 4;
        if (n_quads > 0) {
            int blocks = (n_quads + 255) / 256;

            cudaLaunchConfig_t cfg = {};
            cfg.gridDim  = dim3((unsigned)blocks, 1, 1);
            cfg.blockDim = dim3(256, 1, 1);
            cfg.dynamicSmemBytes = 0;
            cfg.stream = 0;   // same (capturing) stream as the <<<>>> launches

            cudaLaunchAttribute attrs[1];
            attrs[0].id = cudaLaunchAttributeProgrammaticStreamSerialization;
            attrs[0].val.programmaticStreamSerializationAllowed = 1;
            cfg.attrs = attrs;
            cfg.numAttrs = 1;

            cudaLaunchKernelEx(&cfg, edge_kernel, src, dst, out, n_quads);
        }
        int tail_start = n_quads * 4;
        int tail = n_edges - tail_start;
        if (tail > 0)
            edge_kernel_tail<<<(tail + 255) / 256, 256>>>(src, dst, out,
                                                          tail_start, n_edges);
    }
}

// round 15
// speedup vs baseline: 1.2120x; 1.0247x over previous
#include <cuda_runtime.h>
#include <math.h>

#define D 128
#define MAX_NODES 131072   // >= 100000 actual

// Per-node projections. g_pu has the bias folded in (saves a per-edge FADD
// and the bias load in the edge kernel).
__device__ float g_pu[MAX_NODES];
__device__ float g_pv[MAX_NODES];

// ---------------------------------------------------------------------------
// Kernel 1: projections. 8 lanes per node, 4 nodes per warp.
// Measured at the HBM stream roofline (~6.5 TB/s, 81% of spec).
// Fires the PDL trigger immediately after its stores so the dependent edge
// grid begins launching while proj blocks drain.
// ---------------------------------------------------------------------------
__global__ __launch_bounds__(256) void proj_kernel(
    const float* __restrict__ h,
    const float* __restrict__ W,    // [256]: Wu=W[0:128], Wv=W[128:256]
    const float* __restrict__ bias,
    int n_nodes)
{
    int lane = threadIdx.x & 31;
    int sub  = lane >> 3;
    int c    = lane & 7;

    const float4* Wu4 = reinterpret_cast<const float4*>(W);
    const float4* Wv4 = reinterpret_cast<const float4*>(W + D);
    float4 wu[4], wv[4];
    #pragma unroll
    for (int it = 0; it < 4; it++) {
        wu[it] = Wu4[it * 8 + c];
        wv[it] = Wv4[it * 8 + c];
    }

    int gwarp = (blockIdx.x * blockDim.x + threadIdx.x) >> 5;
    int node  = gwarp * 4 + sub;

    float su = 0.0f, sv = 0.0f;
    if (node < n_nodes) {
        const float4* hp = reinterpret_cast<const float4*>(h + (size_t)node * D);
        float4 hv[4];
        #pragma unroll
        for (int it = 0; it < 4; it++)
            hv[it] = __ldcs(&hp[it * 8 + c]);   // h streamed exactly once
        #pragma unroll
        for (int it = 0; it < 4; it++) {
            su += hv[it].x * wu[it].x + hv[it].y * wu[it].y
                + hv[it].z * wu[it].z + hv[it].w * wu[it].w;
            sv += hv[it].x * wv[it].x + hv[it].y * wv[it].y
                + hv[it].z * wv[it].z + hv[it].w * wv[it].w;
        }
    }

    #pragma unroll
    for (int o = 4; o >= 1; o >>= 1) {
        su += __shfl_xor_sync(0xFFFFFFFFu, su, o);
        sv += __shfl_xor_sync(0xFFFFFFFFu, sv, o);
    }
    if (c == 0 && node < n_nodes) {
        g_pu[node] = su + bias[0];   // bias folded into pu
        g_pv[node] = sv;
    }

    // Early PDL trigger: this block's writes are issued; allow the dependent
    // edge grid to start launching. Visibility is still enforced by the
    // consumer's cudaGridDependencySynchronize().
    cudaTriggerProgrammaticLaunchCompletion();
}

// ---------------------------------------------------------------------------
// Kernel 2: per-edge score — proven optimal shape (4 edges/thread, 256-thr
// blocks, plain loads; fastest of 7 tested mechanisms), PDL-enabled: runs its
// proj-independent preamble (index loads) during proj's drain, then syncs
// before the pu/pv gathers. Correct with or without PDL taking effect.
// ---------------------------------------------------------------------------
__global__ __launch_bounds__(256) void edge_kernel(
    const int*  __restrict__ src,
    const int*  __restrict__ dst,
    float* __restrict__ out,
    int n_quads)                   // total_edges / 4
{
    int i = blockIdx.x * blockDim.x + threadIdx.x;
    bool active = (i < n_quads);

    // Preamble: independent of proj output — overlaps proj's tail under PDL
    int4 s = make_int4(0, 0, 0, 0), d = make_int4(0, 0, 0, 0);
    if (active) {
        s = reinterpret_cast<const int4*>(src)[i];
        d = reinterpret_cast<const int4*>(dst)[i];
    }

    cudaGridDependencySynchronize();   // wait for proj's pu/pv writes

    if (!active) return;

    // All 8 gathers issued before any dependent math
    float u0 = g_pu[s.x], u1 = g_pu[s.y], u2 = g_pu[s.z], u3 = g_pu[s.w];
    float v0 = g_pv[d.x], v1 = g_pv[d.y], v2 = g_pv[d.z], v3 = g_pv[d.w];

    float4 o;
    o.x = 1.0f / (1.0f + expf(-(u0 + v0)));
    o.y = 1.0f / (1.0f + expf(-(u1 + v1)));
    o.z = 1.0f / (1.0f + expf(-(u2 + v2)));
    o.w = 1.0f / (1.0f + expf(-(u3 + v3)));

    reinterpret_cast<float4*>(out)[i] = o;
}

// Scalar tail (unused when n_edges % 4 == 0; 1.6M % 4 == 0)
__global__ void edge_kernel_tail(
    const int*  __restrict__ src,
    const int*  __restrict__ dst,
    float* __restrict__ out,
    int start, int n_edges)
{
    int i = start + blockIdx.x * blockDim.x + threadIdx.x;
    if (i >= n_edges) return;
    float x = g_pu[src[i]] + g_pv[dst[i]];   // bias already folded into pu
    out[i] = 1.0f / (1.0f + expf(-x));
}

extern "C" void kernel_launch(void* const* d_in, const int* in_sizes, int n_in,
                              void* d_out, int out_size)
{
    const float* h      = (const float*)d_in[0];
    const int*   src    = (const int*)  d_in[1];
    const int*   dst    = (const int*)  d_in[2];
    const float* W      = (const float*)d_in[3];
    const float* W_bias = (const float*)d_in[4];
    float* out          = (float*)d_out;

    int n_nodes = in_sizes[0] / D;
    int n_edges = in_sizes[1];

    // Kernel 1: projections (4 nodes per warp)
    {
        int n_groups = (n_nodes + 3) / 4;
        int blocks = (n_groups * 32 + 255) / 256;
        proj_kernel<<<blocks, 256>>>(h, W, W_bias, n_nodes);
    }

    // Kernel 2: PDL launch — overlaps its preamble with proj's drain
    {
        int n_quads = n_edges / 4;
        if (n_quads > 0) {
            int blocks = (n_quads + 255) / 256;

            cudaLaunchConfig_t cfg = {};
            cfg.gridDim  = dim3((unsigned)blocks, 1, 1);
            cfg.blockDim = dim3(256, 1, 1);
            cfg.dynamicSmemBytes = 0;
            cfg.stream = 0;   // same (capturing) stream as the <<<>>> launches

            cudaLaunchAttribute attrs[1];
            attrs[0].id = cudaLaunchAttributeProgrammaticStreamSerialization;
            attrs[0].val.programmaticStreamSerializationAllowed = 1;
            cfg.attrs = attrs;
            cfg.numAttrs = 1;

            cudaLaunchKernelEx(&cfg, edge_kernel, src, dst, out, n_quads);
        }
        int tail_start = n_quads * 4;
        int tail = n_edges - tail_start;
        if (tail > 0)
            edge_kernel_tail<<<(tail + 255) / 256, 256>>>(src, dst, out,
                                                          tail_start, n_edges);
    }
}

// round 16
// speedup vs baseline: 1.2135x; 1.0013x over previous
#include <cuda_runtime.h>
#include <math.h>

#define D 128
#define MAX_NODES 131072   // >= 100000 actual

// Per-node projections. g_pu has the bias folded in (saves a per-edge FADD
// and the bias load in the edge kernel).
__device__ float g_pu[MAX_NODES];
__device__ float g_pv[MAX_NODES];

// ---------------------------------------------------------------------------
// Kernel 1: projections. 8 lanes per node, 4 nodes per warp.
// Measured at the HBM stream roofline (~6.5 TB/s, 81% of spec).
// Fires the PDL trigger immediately after its stores so the dependent edge
// grid begins launching while proj blocks drain.
// ---------------------------------------------------------------------------
__global__ __launch_bounds__(256) void proj_kernel(
    const float* __restrict__ h,
    const float* __restrict__ W,    // [256]: Wu=W[0:128], Wv=W[128:256]
    const float* __restrict__ bias,
    int n_nodes)
{
    int lane = threadIdx.x & 31;
    int sub  = lane >> 3;
    int c    = lane & 7;

    const float4* Wu4 = reinterpret_cast<const float4*>(W);
    const float4* Wv4 = reinterpret_cast<const float4*>(W + D);
    float4 wu[4], wv[4];
    #pragma unroll
    for (int it = 0; it < 4; it++) {
        wu[it] = Wu4[it * 8 + c];
        wv[it] = Wv4[it * 8 + c];
    }

    int gwarp = (blockIdx.x * blockDim.x + threadIdx.x) >> 5;
    int node  = gwarp * 4 + sub;

    float su = 0.0f, sv = 0.0f;
    if (node < n_nodes) {
        const float4* hp = reinterpret_cast<const float4*>(h + (size_t)node * D);
        float4 hv[4];
        #pragma unroll
        for (int it = 0; it < 4; it++)
            hv[it] = __ldcs(&hp[it * 8 + c]);   // h streamed exactly once
        #pragma unroll
        for (int it = 0; it < 4; it++) {
            su += hv[it].x * wu[it].x + hv[it].y * wu[it].y
                + hv[it].z * wu[it].z + hv[it].w * wu[it].w;
            sv += hv[it].x * wv[it].x + hv[it].y * wv[it].y
                + hv[it].z * wv[it].z + hv[it].w * wv[it].w;
        }
    }

    #pragma unroll
    for (int o = 4; o >= 1; o >>= 1) {
        su += __shfl_xor_sync(0xFFFFFFFFu, su, o);
        sv += __shfl_xor_sync(0xFFFFFFFFu, sv, o);
    }
    if (c == 0 && node < n_nodes) {
        g_pu[node] = su + bias[0];   // bias folded into pu
        g_pv[node] = sv;
    }

    // Early PDL trigger: this block's writes are issued; allow the dependent
    // edge grid to start launching. Visibility is still enforced by the
    // consumer's cudaGridDependencySynchronize().
    cudaTriggerProgrammaticLaunchCompletion();
}

// ---------------------------------------------------------------------------
// Kernel 2: per-edge score — proven optimal shape (4 edges/thread, 256-thr
// blocks, plain loads; fastest of 7 tested mechanisms), PDL-enabled: runs its
// proj-independent preamble (index loads) during proj's drain, then syncs
// before the pu/pv gathers. Correct with or without PDL taking effect.
// ---------------------------------------------------------------------------
__global__ __launch_bounds__(256) void edge_kernel(
    const int*  __restrict__ src,
    const int*  __restrict__ dst,
    float* __restrict__ out,
    int n_quads)                   // total_edges / 4
{
    int i = blockIdx.x * blockDim.x + threadIdx.x;
    bool active = (i < n_quads);

    // Preamble: independent of proj output — overlaps proj's tail under PDL
    int4 s = make_int4(0, 0, 0, 0), d = make_int4(0, 0, 0, 0);
    if (active) {
        s = reinterpret_cast<const int4*>(src)[i];
        d = reinterpret_cast<const int4*>(dst)[i];
    }

    cudaGridDependencySynchronize();   // wait for proj's pu/pv writes

    if (!active) return;

    // All 8 gathers issued before any dependent math
    float u0 = g_pu[s.x], u1 = g_pu[s.y], u2 = g_pu[s.z], u3 = g_pu[s.w];
    float v0 = g_pv[d.x], v1 = g_pv[d.y], v2 = g_pv[d.z], v3 = g_pv[d.w];

    float4 o;
    o.x = 1.0f / (1.0f + expf(-(u0 + v0)));
    o.y = 1.0f / (1.0f + expf(-(u1 + v1)));
    o.z = 1.0f / (1.0f + expf(-(u2 + v2)));
    o.w = 1.0f / (1.0f + expf(-(u3 + v3)));

    reinterpret_cast<float4*>(out)[i] = o;
}

// Scalar tail (unused when n_edges % 4 == 0; 1.6M % 4 == 0)
__global__ void edge_kernel_tail(
    const int*  __restrict__ src,
    const int*  __restrict__ dst,
    float* __restrict__ out,
    int start, int n_edges)
{
    int i = start + blockIdx.x * blockDim.x + threadIdx.x;
    if (i >= n_edges) return;
    float x = g_pu[src[i]] + g_pv[dst[i]];   // bias already folded into pu
    out[i] = 1.0f / (1.0f + expf(-x));
}

extern "C" void kernel_launch(void* const* d_in, const int* in_sizes, int n_in,
                              void* d_out, int out_size)
{
    const float* h      = (const float*)d_in[0];
    const int*   src    = (const int*)  d_in[1];
    const int*   dst    = (const int*)  d_in[2];
    const float* W      = (const float*)d_in[3];
    const float* W_bias = (const float*)d_in[4];
    float* out          = (float*)d_out;

    int n_nodes = in_sizes[0] / D;
    int n_edges = in_sizes[1];

    // Kernel 1: projections (4 nodes per warp)
    {
        int n_groups = (n_nodes + 3) / 4;
        int blocks = (n_groups * 32 + 255) / 256;
        proj_kernel<<<blocks, 256>>>(h, W, W_bias, n_nodes);
    }

    // Kernel 2: PDL launch — overlaps its preamble with proj's drain
    {
        int n_quads = n_edges / 4;
        if (n_quads > 0) {
            int blocks = (n_quads + 255) / 256;

            cudaLaunchConfig_t cfg = {};
            cfg.gridDim  = dim3((unsigned)blocks, 1, 1);
            cfg.blockDim = dim3(256, 1, 1);
            cfg.dynamicSmemBytes = 0;
            cfg.stream = 0;   // same (capturing) stream as the <<<>>> launches

            cudaLaunchAttribute attrs[1];
            attrs[0].id = cudaLaunchAttributeProgrammaticStreamSerialization;
            attrs[0].val.programmaticStreamSerializationAllowed = 1;
            cfg.attrs = attrs;
            cfg.numAttrs = 1;

            cudaLaunchKernelEx(&cfg, edge_kernel, src, dst, out, n_quads);
        }
        int tail_start = n_quads * 4;
        int tail = n_edges - tail_start;
        if (tail > 0)
            edge_kernel_tail<<<(tail + 255) / 256, 256>>>(src, dst, out,
                                                          tail_start, n_edges);
    }
}